// round 6
// baseline (speedup 1.0000x reference)
#include <cuda_runtime.h>
#include <cstdint>

// AdditiveAttention: B=2, L=512, S=512, H=8, E=32, D=64 (fp32)
// score = sum_e v_e*tanh(q+k) + mask + klen ; tanh(x) = 1 - 2/(1+e^{2x})
// e^{2x} = e^{2q}*e^{2k} (precomputed).
// Quad combine via A=1+u only:  v0/A0+v1/A1 = (v0*A1+v1*A0)/(A0*A1)
//   -> 12 FMA-instr + 1 rcp per 4 elems.  5 quad + 3 packed-simple groups
//   balance FMA (144 cyc/j) vs MUFU (136 cyc/j) per warp.
// exp fused into phase 1 (scores bounded by sum|v| -> no max pass).

namespace {
constexpr int B = 2, L = 512, S = 512, H = 8, E = 32, D = 64;
constexpr int TL = 64;
constexpr int THREADS = 512;
constexpr int SC_STRIDE = 524;
constexpr int KS_STRIDE = E + 4;   // 36
constexpr int VS_STRIDE = 68;
constexpr int PB_STRIDE = 68;
constexpr int SMEM_FLOATS = TL * SC_STRIDE + S * KS_STRIDE + 64 * VS_STRIDE + TL;
constexpr int SMEM_BYTES = SMEM_FLOATS * (int)sizeof(float);
constexpr float TWO_LOG2E = 2.885390081777927f; // 2*log2(e)
constexpr float LOG2E = 1.4426950408889634f;
}

using u64 = unsigned long long;

__device__ __forceinline__ float ex2f(float x) {
    float y; asm("ex2.approx.f32 %0, %1;" : "=f"(y) : "f"(x)); return y;
}
__device__ __forceinline__ float rcpf(float x) {
    float y; asm("rcp.approx.f32 %0, %1;" : "=f"(y) : "f"(x)); return y;
}
__device__ __forceinline__ u64 pk(float a, float b) {
    u64 d; asm("mov.b64 %0, {%1, %2};" : "=l"(d) : "f"(a), "f"(b)); return d;
}
__device__ __forceinline__ void upk(u64 d, float& a, float& b) {
    asm("mov.b64 {%0, %1}, %2;" : "=f"(a), "=f"(b) : "l"(d));
}
__device__ __forceinline__ u64 fma2(u64 a, u64 b, u64 c) {
    u64 d; asm("fma.rn.f32x2 %0, %1, %2, %3;" : "=l"(d) : "l"(a), "l"(b), "l"(c)); return d;
}

__global__ void __launch_bounds__(THREADS, 1)
addattn_kernel(const float* __restrict__ q, const float* __restrict__ k,
               const float* __restrict__ vals, const float* __restrict__ vvec,
               const float* __restrict__ mask, const float* __restrict__ klen,
               float* __restrict__ out)
{
    extern __shared__ float sm[];
    float* sc   = sm;                     // [TL][SC_STRIDE] unnormalized probs
    float* ks   = sc + TL * SC_STRIDE;    // [S][KS_STRIDE] exp2(c*k); reused as pbuf
    float* vs   = ks + S * KS_STRIDE;     // [64][VS_STRIDE] values chunk
    float* rsum = vs + 64 * VS_STRIDE;    // [TL] 1/rowsum

    const int tid = threadIdx.x;
    const int bid = blockIdx.x;
    const int lb = bid & 7;
    const int h  = (bid >> 3) & 7;
    const int b  = bid >> 6;
    const int l0 = lb * TL;

    // ---- stage keys as Ek = exp2(c*k) into smem ----
    for (int i = tid; i < S * (E / 4); i += THREADS) {
        int s = i >> 3, e4 = i & 7;
        float4 t = reinterpret_cast<const float4*>(
            k + ((size_t)((b * S + s) * H + h)) * E)[e4];
        t.x = ex2f(TWO_LOG2E * t.x); t.y = ex2f(TWO_LOG2E * t.y);
        t.z = ex2f(TWO_LOG2E * t.z); t.w = ex2f(TWO_LOG2E * t.w);
        *reinterpret_cast<float4*>(ks + s * KS_STRIDE + e4 * 4) = t;
    }

    const int l   = tid >> 3;   // 0..63 local L row
    const int sof = tid & 7;

    // ---- per-thread constants ----
    u64   qp01[8], qp23[8];                 // packed Eq pairs (thread-varying)
    float v0c[5], v1c[5], v2c[5], v3c[5];   // quad groups 0..4 (uniform)
    u64   vp01s[3], vp23s[3];               // simple groups 5..7 (uniform)
    float vsumtot = 0.f;
    {
        const float4* qg = reinterpret_cast<const float4*>(
            q + ((size_t)((b * L + l0 + l) * H + h)) * E);
        const float4* vg = reinterpret_cast<const float4*>(vvec);
#pragma unroll
        for (int e4 = 0; e4 < 8; ++e4) {
            float4 t = qg[e4];
            float q0 = ex2f(t.x * TWO_LOG2E), q1 = ex2f(t.y * TWO_LOG2E);
            float q2 = ex2f(t.z * TWO_LOG2E), q3 = ex2f(t.w * TWO_LOG2E);
            qp01[e4] = pk(q0, q1);
            qp23[e4] = pk(q2, q3);
            float4 u = vg[e4];
            vsumtot += (u.x + u.y) + (u.z + u.w);
            if (e4 < 5) {
                v0c[e4] = u.x; v1c[e4] = u.y; v2c[e4] = u.z; v3c[e4] = u.w;
            } else {
                vp01s[e4 - 5] = pk(u.x, u.y);
                vp23s[e4 - 5] = pk(u.z, u.w);
            }
        }
    }
    __syncthreads();

    const u64 ONES2 = pk(1.f, 1.f);

    // ---- phase 1: p = exp(score) fused; per-thread row partial sum ----
    {
        const float* maskrow = mask + (size_t)(l0 + l) * S;
        const float* klrow   = klen + (size_t)b * S;
        const float baseL = vsumtot * LOG2E;
        float psum = 0.f;
#pragma unroll 2
        for (int j = 0; j < S / 8; ++j) {
            int s = 8 * j + sof;
            const ulonglong2* kr = reinterpret_cast<const ulonglong2*>(ks + s * KS_STRIDE);
            float accP0 = 0.f, accP1 = 0.f;
            u64 accV = pk(0.f, 0.f);
#pragma unroll
            for (int g = 0; g < 5; ++g) {      // quad groups: 1 rcp / 4 elems
                ulonglong2 kk2 = kr[g];
                u64 A2 = fma2(qp01[g], kk2.x, ONES2);   // (1+u0, 1+u1)
                u64 B2 = fma2(qp23[g], kk2.y, ONES2);   // (1+u2, 1+u3)
                float A0, A1, B0, B1; upk(A2, A0, A1); upk(B2, B0, B1);
                float denA = A0 * A1;
                float denB = B0 * B1;
                float numA = fmaf(v0c[g], A1, v1c[g] * A0);
                float numB = fmaf(v2c[g], B1, v3c[g] * B0);
                float num = fmaf(numA, denB, numB * denA);
                float den = denA * denB;
                if (g & 1) accP1 = fmaf(num, rcpf(den), accP1);
                else       accP0 = fmaf(num, rcpf(den), accP0);
            }
#pragma unroll
            for (int g = 5; g < 8; ++g) {      // packed-simple groups
                ulonglong2 kk2 = kr[g];
                u64 d01 = fma2(qp01[g], kk2.x, ONES2);
                u64 d23 = fma2(qp23[g], kk2.y, ONES2);
                float a0, a1, a2, a3; upk(d01, a0, a1); upk(d23, a2, a3);
                u64 r01 = pk(rcpf(a0), rcpf(a1));
                u64 r23 = pk(rcpf(a2), rcpf(a3));
                accV = fma2(vp01s[g - 5], r01, accV);
                accV = fma2(vp23s[g - 5], r23, accV);
            }
            float vlo, vhi; upk(accV, vlo, vhi);
            float a = (accP0 + accP1) + (vlo + vhi);
            float mk = maskrow[s] + klrow[s];
            float p = ex2f(fmaf(-2.f * LOG2E, a, fmaf(LOG2E, mk, baseL)));
            psum += p;
            sc[l * SC_STRIDE + s] = p;
        }
        psum += __shfl_xor_sync(0xffffffffu, psum, 1);
        psum += __shfl_xor_sync(0xffffffffu, psum, 2);
        psum += __shfl_xor_sync(0xffffffffu, psum, 4);
        if (sof == 0) rsum[l] = rcpf(psum);
    }
    __syncthreads();

    // ---- phase 3: 4x8 register tile per thread, 4 s-subgroups, packed FMA ----
    {
        const int sgrp = tid >> 7;
        const int tt   = tid & 127;
        const int rg   = tt >> 3;
        const int cg   = tt & 7;

        u64 acc2[4][4];
#pragma unroll
        for (int i = 0; i < 4; ++i)
#pragma unroll
            for (int m = 0; m < 4; ++m) acc2[i][m] = pk(0.f, 0.f);

        for (int c = 0; c < 8; ++c) {
            for (int i = tid; i < 64 * (D / 4); i += THREADS) {
                int ss = i >> 4, d4 = i & 15;
                float4 t = reinterpret_cast<const float4*>(
                    vals + ((size_t)((b * S + c * 64 + ss) * H + h)) * D)[d4];
                *reinterpret_cast<float4*>(vs + ss * VS_STRIDE + d4 * 4) = t;
            }
            __syncthreads();

            const float* Pb = sc + (4 * rg) * SC_STRIDE + c * 64 + 16 * sgrp;
            const float* Vb = vs + (16 * sgrp) * VS_STRIDE + 8 * cg;
#pragma unroll
            for (int jb = 0; jb < 16; jb += 4) {
                float p4[4][4];
#pragma unroll
                for (int i = 0; i < 4; ++i) {
                    float4 p = *reinterpret_cast<const float4*>(Pb + i * SC_STRIDE + jb);
                    p4[i][0] = p.x; p4[i][1] = p.y; p4[i][2] = p.z; p4[i][3] = p.w;
                }
#pragma unroll
                for (int u = 0; u < 4; ++u) {
                    const ulonglong2* vrow =
                        reinterpret_cast<const ulonglong2*>(Vb + (jb + u) * VS_STRIDE);
                    ulonglong2 va = vrow[0];
                    ulonglong2 vb2 = vrow[1];
#pragma unroll
                    for (int i = 0; i < 4; ++i) {
                        u64 pp = pk(p4[i][u], p4[i][u]);
                        acc2[i][0] = fma2(va.x,  pp, acc2[i][0]);
                        acc2[i][1] = fma2(va.y,  pp, acc2[i][1]);
                        acc2[i][2] = fma2(vb2.x, pp, acc2[i][2]);
                        acc2[i][3] = fma2(vb2.y, pp, acc2[i][3]);
                    }
                }
            }
            __syncthreads();
        }

        float* pbuf = ks;  // [4][64][PB_STRIDE]
#pragma unroll
        for (int i = 0; i < 4; ++i) {
            int row = 4 * rg + i;
            u64* dst = reinterpret_cast<u64*>(
                pbuf + (sgrp * 64 + row) * PB_STRIDE + 8 * cg);
            reinterpret_cast<ulonglong2*>(dst)[0] = make_ulonglong2(acc2[i][0], acc2[i][1]);
            reinterpret_cast<ulonglong2*>(dst)[1] = make_ulonglong2(acc2[i][2], acc2[i][3]);
        }
        __syncthreads();

        {
            int row = tid >> 3;
            int c8  = (tid & 7) * 8;
            const float* p0 = pbuf + (0 * 64 + row) * PB_STRIDE + c8;
            const float* p1 = pbuf + (1 * 64 + row) * PB_STRIDE + c8;
            const float* p2 = pbuf + (2 * 64 + row) * PB_STRIDE + c8;
            const float* p3 = pbuf + (3 * 64 + row) * PB_STRIDE + c8;
            float r = rsum[row];
            float* og = out + ((size_t)((b * L + l0 + row) * H + h)) * D + c8;
#pragma unroll
            for (int half = 0; half < 2; ++half) {
                float4 a0 = *reinterpret_cast<const float4*>(p0 + 4 * half);
                float4 a1 = *reinterpret_cast<const float4*>(p1 + 4 * half);
                float4 a2 = *reinterpret_cast<const float4*>(p2 + 4 * half);
                float4 a3 = *reinterpret_cast<const float4*>(p3 + 4 * half);
                float4 o;
                o.x = ((a0.x + a1.x) + (a2.x + a3.x)) * r;
                o.y = ((a0.y + a1.y) + (a2.y + a3.y)) * r;
                o.z = ((a0.z + a1.z) + (a2.z + a3.z)) * r;
                o.w = ((a0.w + a1.w) + (a2.w + a3.w)) * r;
                *reinterpret_cast<float4*>(og + 4 * half) = o;
            }
        }
    }
}

extern "C" void kernel_launch(void* const* d_in, const int* in_sizes, int n_in,
                              void* d_out, int out_size)
{
    (void)in_sizes; (void)n_in; (void)out_size;
    cudaFuncSetAttribute(addattn_kernel,
                         cudaFuncAttributeMaxDynamicSharedMemorySize, SMEM_BYTES);
    const float* q    = (const float*)d_in[0];
    const float* k    = (const float*)d_in[1];
    const float* vals = (const float*)d_in[2];
    const float* vvec = (const float*)d_in[3];
    const float* mask = (const float*)d_in[4];
    const float* klen = (const float*)d_in[5];
    addattn_kernel<<<B * H * (L / TL), THREADS, SMEM_BYTES>>>(
        q, k, vals, vvec, mask, klen, (float*)d_out);
}